// round 16
// baseline (speedup 1.0000x reference)
#include <cuda_runtime.h>
#include <cuda_bf16.h>
#include <math.h>
#include <math_constants.h>
#include <stdint.h>

// ---------------------------------------------------------------------------
// Problem constants
// ---------------------------------------------------------------------------
static constexpr int T_SEQ   = 2048;
static constexpr int D_MODEL = 4096;
static constexpr int NHQ     = 32;
static constexpr int NKV     = 8;
static constexpr int HD      = 128;
static constexpr int NQKV    = NHQ * HD + 2 * NKV * HD;   // 6144
static constexpr int KCOL0   = NHQ * HD;                  // 4096
static constexpr int VCOL0   = KCOL0 + NKV * HD;          // 5120

// Packed-panel geometry: panel = [128 rows x 32 k] bf16, rows padded to 80B.
static constexpr int PANEL_B   = 10240;
static constexpr int PANEL_U4  = 640;
static constexpr int KPAN      = 128;      // 4096/32 k-panels per GEMM matrix

// ---------------------------------------------------------------------------
// Scratch (device globals -- sanctioned scratch mechanism)
// ---------------------------------------------------------------------------
__device__ uint4 pk_xhi[(size_t)16 * KPAN * PANEL_U4];   // x packed
__device__ uint4 pk_xlo[(size_t)16 * KPAN * PANEL_U4];
__device__ uint4 pk_ahi[(size_t)16 * KPAN * PANEL_U4];   // attention out packed
__device__ uint4 pk_alo[(size_t)16 * KPAN * PANEL_U4];
__device__ uint4 pk_wqh[(size_t)48 * KPAN * PANEL_U4];   // qkv weights
__device__ uint4 pk_wql[(size_t)48 * KPAN * PANEL_U4];
__device__ uint4 pk_woh[(size_t)32 * KPAN * PANEL_U4];   // o_w
__device__ uint4 pk_wol[(size_t)32 * KPAN * PANEL_U4];

// attention operand panels (written by the fused QKV epilogue):
__device__ uint4 pk_qhi[(size_t)32 * 16 * 4 * PANEL_U4];
__device__ uint4 pk_qlo[(size_t)32 * 16 * 4 * PANEL_U4];
__device__ uint4 pk_khi[(size_t)8 * 16 * 4 * PANEL_U4];
__device__ uint4 pk_klo[(size_t)8 * 16 * 4 * PANEL_U4];
__device__ uint4 pk_vhi[(size_t)8 * 16 * 4 * PANEL_U4];
__device__ uint4 pk_vlo[(size_t)8 * 16 * 4 * PANEL_U4];

// ---------------------------------------------------------------------------
// PTX helpers (sm_80-era features only; valid at compute_103 base target)
// ---------------------------------------------------------------------------
__device__ __forceinline__ uint32_t smem_u32(const void* p) {
    uint32_t a;
    asm("{ .reg .u64 t; cvta.to.shared.u64 t, %1; cvt.u32.u64 %0, t; }" : "=r"(a) : "l"(p));
    return a;
}

#define LDM4(r, a)                                                            \
    asm volatile("ldmatrix.sync.aligned.m8n8.x4.shared.b16 {%0,%1,%2,%3}, [%4];" \
        : "=r"((r)[0]), "=r"((r)[1]), "=r"((r)[2]), "=r"((r)[3]) : "r"(a))

#define LDM4T(r, a)                                                           \
    asm volatile("ldmatrix.sync.aligned.m8n8.x4.trans.shared.b16 {%0,%1,%2,%3}, [%4];" \
        : "=r"((r)[0]), "=r"((r)[1]), "=r"((r)[2]), "=r"((r)[3]) : "r"(a))

#define MMA(d, a, b0, b1)                                                     \
    asm volatile("mma.sync.aligned.m16n8k16.row.col.f32.bf16.bf16.f32 "       \
        "{%0,%1,%2,%3},{%4,%5,%6,%7},{%8,%9},{%0,%1,%2,%3};"                  \
        : "+f"((d)[0]), "+f"((d)[1]), "+f"((d)[2]), "+f"((d)[3])              \
        : "r"((a)[0]), "r"((a)[1]), "r"((a)[2]), "r"((a)[3]), "r"(b0), "r"(b1))

__device__ __forceinline__ void cp16(uint32_t dst, const void* src) {
    asm volatile("cp.async.cg.shared.global [%0], [%1], 16;" :: "r"(dst), "l"(src));
}
__device__ __forceinline__ void cp_commit() { asm volatile("cp.async.commit_group;" ::: "memory"); }
template <int N> __device__ __forceinline__ void cp_wait() {
    asm volatile("cp.async.wait_group %0;" :: "n"(N) : "memory");
}

__device__ __forceinline__ void split2(float x, __nv_bfloat16& h, __nv_bfloat16& l) {
    h = __float2bfloat16_rn(x);
    l = __float2bfloat16_rn(x - __bfloat162float(h));
}
__device__ __forceinline__ void pack_split(float f0, float f1, uint32_t& h, uint32_t& l) {
    __nv_bfloat16 h0, l0, h1, l1;
    split2(f0, h0, l0);
    split2(f1, h1, l1);
    h = ((uint32_t)__bfloat16_as_ushort(h1) << 16) | __bfloat16_as_ushort(h0);
    l = ((uint32_t)__bfloat16_as_ushort(l1) << 16) | __bfloat16_as_ushort(l0);
}

__device__ __forceinline__ size_t pk_idx(int row, int kchunk16) {
    const int rb = row >> 7, r = row & 127;
    const int kc = kchunk16 >> 2, c = kchunk16 & 3;
    return ((size_t)(rb * KPAN + kc)) * PANEL_U4 + r * 5 + c;
}

// ---------------------------------------------------------------------------
// Kernel A: pack x -> bf16 hi/lo panels
// ---------------------------------------------------------------------------
__global__ __launch_bounds__(256) void pack_x_kernel(const float* __restrict__ x)
{
    const int gid = blockIdx.x * 256 + threadIdx.x;
    const int row = gid >> 9, kch = gid & 511;
    const float* s = x + (size_t)row * D_MODEL + kch * 8;
    float4 a = *reinterpret_cast<const float4*>(s);
    float4 b = *reinterpret_cast<const float4*>(s + 4);
    float v[8] = {a.x, a.y, a.z, a.w, b.x, b.y, b.z, b.w};
    __nv_bfloat16 h8[8], l8[8];
#pragma unroll
    for (int i = 0; i < 8; i++) split2(v[i], h8[i], l8[i]);
    const size_t idx = pk_idx(row, kch);
    pk_xhi[idx] = *reinterpret_cast<uint4*>(h8);
    pk_xlo[idx] = *reinterpret_cast<uint4*>(l8);
}

// ---------------------------------------------------------------------------
// Kernel B1: pack qkv weights (writes device globals directly)
// ---------------------------------------------------------------------------
__global__ __launch_bounds__(256) void pack_wq_kernel(
    const float* __restrict__ src, int row0)
{
    __shared__ float t[32][33];
    const int tx = threadIdx.x, ty = threadIdx.y;
    const int d0 = blockIdx.x * 32, h0 = blockIdx.y * 32, z = blockIdx.z;
    const float* s = src + (size_t)z * D_MODEL * HD;
#pragma unroll
    for (int j = 0; j < 4; j++)
        t[ty + 8 * j][tx] = s[(size_t)(d0 + ty + 8 * j) * HD + h0 + tx];
    __syncthreads();
    const int tid = ty * 32 + tx;
    if (tid < 128) {
        const int h_in = tid >> 2, cj = tid & 3;
        const int row = row0 + z * HD + h0 + h_in;
        __nv_bfloat16 h8[8], l8[8];
#pragma unroll
        for (int i = 0; i < 8; i++) split2(t[cj * 8 + i][h_in], h8[i], l8[i]);
        const size_t idx = pk_idx(row, (d0 >> 3) + cj);
        pk_wqh[idx] = *reinterpret_cast<uint4*>(h8);
        pk_wql[idx] = *reinterpret_cast<uint4*>(l8);
    }
}

// ---------------------------------------------------------------------------
// Kernel B2: pack o_w
// ---------------------------------------------------------------------------
__global__ __launch_bounds__(256) void pack_wo_kernel(const float* __restrict__ src)
{
    __shared__ float t[32][33];
    const int tx = threadIdx.x, ty = threadIdx.y;
    const int nh0 = blockIdx.x * 32, d0 = blockIdx.y * 32;
#pragma unroll
    for (int j = 0; j < 4; j++)
        t[ty + 8 * j][tx] = src[(size_t)(nh0 + ty + 8 * j) * D_MODEL + d0 + tx];
    __syncthreads();
    const int tid = ty * 32 + tx;
    if (tid < 128) {
        const int d_in = tid >> 2, cj = tid & 3;
        const int row = d0 + d_in;
        __nv_bfloat16 h8[8], l8[8];
#pragma unroll
        for (int i = 0; i < 8; i++) split2(t[cj * 8 + i][d_in], h8[i], l8[i]);
        const size_t idx = pk_idx(row, (nh0 >> 3) + cj);
        pk_woh[idx] = *reinterpret_cast<uint4*>(h8);
        pk_wol[idx] = *reinterpret_cast<uint4*>(l8);
    }
}

// ---------------------------------------------------------------------------
// Kernel C: split-bf16 HMMA GEMM, 128x256 CTA tile (64x64 warp tiles),
// 3-stage cp.async ring, one barrier per chunk, pass-major MMA order.
// MODE 0: plain fp32 epilogue to C.
// MODE 1: fused QKV epilogue -- tile staged through smem, RMSNorm(+scale)
//         + RoPE + bf16 hi/lo split, written straight to pk_q/k/v panels.
//         (Each (row, head) vector is fully inside one CTA: 256 cols = 2 heads.)
// ---------------------------------------------------------------------------
static constexpr int G_STAGE_B  = 6 * PANEL_B;             // 61440
static constexpr int GEMM_SMEM  = 3 * G_STAGE_B;           // 184320
static constexpr int CS_STRIDE  = 264;                     // fp32 tile row stride

template <int MODE>
__global__ __launch_bounds__(256, 1) void gemm_mma_kernel(
    const char* __restrict__ Ah, const char* __restrict__ Al,
    const char* __restrict__ Bh, const char* __restrict__ Bl,
    float* __restrict__ C, int ldc,
    const int*   __restrict__ segment_pos,
    const float* __restrict__ q_scale,
    const float* __restrict__ k_scale)
{
    extern __shared__ char smraw[];
    const uint32_t sb = smem_u32(smraw);
    const int tid = threadIdx.x, wid = tid >> 5, lane = tid & 31;
    const int bxm = blockIdx.x, byn = blockIdx.y;

    const char* pAh = Ah + (size_t)bxm * KPAN * PANEL_B;
    const char* pAl = Al + (size_t)bxm * KPAN * PANEL_B;
    const char* pBh0 = Bh + (size_t)(2 * byn) * KPAN * PANEL_B;
    const char* pBh1 = Bh + (size_t)(2 * byn + 1) * KPAN * PANEL_B;
    const char* pBl0 = Bl + (size_t)(2 * byn) * KPAN * PANEL_B;
    const char* pBl1 = Bl + (size_t)(2 * byn + 1) * KPAN * PANEL_B;

    auto load_stage = [&](int c) {
        const uint32_t dst = sb + (c % 3) * G_STAGE_B;
        const size_t coff = (size_t)c * PANEL_B;
#pragma unroll
        for (int i = 0; i < 15; i++) {
            const int j = tid + i * 256;
            const int r = j / PANEL_U4;
            const int w = j - r * PANEL_U4;
            const char* s =
                (r == 0) ? pAh : (r == 1) ? pAl :
                (r == 2) ? pBh0 : (r == 3) ? pBh1 :
                (r == 4) ? pBl0 : pBl1;
            cp16(dst + j * 16, s + coff + (size_t)w * 16);
        }
    };

    load_stage(0); cp_commit();
    load_stage(1); cp_commit();

    float acc[4][8][4] = {};
    const int wm = wid >> 2, wn = wid & 3;
    const uint32_t aoff = (uint32_t)((wm * 64 + (lane & 15)) * 80 + (lane >> 4) * 16);
    const uint32_t boff = (uint32_t)((wn * 64 + ((lane >> 4) << 3) + (lane & 7)) * 80
                                     + ((lane >> 3) & 1) * 16);

#pragma unroll 1
    for (int c = 0; c < KPAN; c++) {
        cp_wait<1>();
        __syncthreads();

        if (c + 2 < KPAN) load_stage(c + 2);
        cp_commit();

        const uint32_t base = sb + (c % 3) * G_STAGE_B;
        const uint32_t Abh = base + aoff;
        const uint32_t Abl = Abh + PANEL_B;
        const uint32_t Bbh = base + 2 * PANEL_B + boff;
        const uint32_t Bbl = Bbh + 2 * PANEL_B;

#pragma unroll
        for (int ks = 0; ks < 2; ks++) {
            uint32_t ah[4][4], al[4][4];
#pragma unroll
            for (int mf = 0; mf < 4; mf++) {
                LDM4(ah[mf], Abh + ks * 32 + mf * 1280);
                LDM4(al[mf], Abl + ks * 32 + mf * 1280);
            }
#pragma unroll
            for (int ng = 0; ng < 4; ng++) {
                uint32_t bh[4], bl[4];
                LDM4(bh, Bbh + ks * 32 + ng * 1280);
                LDM4(bl, Bbl + ks * 32 + ng * 1280);
                // pass-major: same-accumulator MMAs separated by 8 indep. ones
#pragma unroll
                for (int mf = 0; mf < 4; mf++)
#pragma unroll
                    for (int hf = 0; hf < 2; hf++)
                        MMA(acc[mf][ng * 2 + hf], ah[mf], bh[hf * 2], bh[hf * 2 + 1]);
#pragma unroll
                for (int mf = 0; mf < 4; mf++)
#pragma unroll
                    for (int hf = 0; hf < 2; hf++)
                        MMA(acc[mf][ng * 2 + hf], ah[mf], bl[hf * 2], bl[hf * 2 + 1]);
#pragma unroll
                for (int mf = 0; mf < 4; mf++)
#pragma unroll
                    for (int hf = 0; hf < 2; hf++)
                        MMA(acc[mf][ng * 2 + hf], al[mf], bh[hf * 2], bh[hf * 2 + 1]);
            }
        }
    }

    const int g = lane >> 2, tg = lane & 3;

    if constexpr (MODE == 0) {
#pragma unroll
        for (int mf = 0; mf < 4; mf++)
#pragma unroll
            for (int nf = 0; nf < 8; nf++) {
                const int r0  = bxm * 128 + wm * 64 + mf * 16 + g;
                const int col = byn * 256 + wn * 64 + nf * 8 + tg * 2;
                *reinterpret_cast<float2*>(C + (size_t)r0 * ldc + col) =
                    make_float2(acc[mf][nf][0], acc[mf][nf][1]);
                *reinterpret_cast<float2*>(C + (size_t)(r0 + 8) * ldc + col) =
                    make_float2(acc[mf][nf][2], acc[mf][nf][3]);
            }
    } else {
        // ---- fused QKV epilogue: smem stage -> norm/rope/split -> panels ----
        cp_wait<0>();
        __syncthreads();                 // stage ring fully retired; smem free
        float* Cs = reinterpret_cast<float*>(smraw);
#pragma unroll
        for (int mf = 0; mf < 4; mf++)
#pragma unroll
            for (int nf = 0; nf < 8; nf++) {
                const int r0  = wm * 64 + mf * 16 + g;
                const int col = wn * 64 + nf * 8 + tg * 2;
                *reinterpret_cast<float2*>(&Cs[(size_t)r0 * CS_STRIDE + col]) =
                    make_float2(acc[mf][nf][0], acc[mf][nf][1]);
                *reinterpret_cast<float2*>(&Cs[(size_t)(r0 + 8) * CS_STRIDE + col]) =
                    make_float2(acc[mf][nf][2], acc[mf][nf][3]);
            }
        __syncthreads();

        // warp wid handles rows wid*16 .. wid*16+15, 2 heads per row
#pragma unroll 1
        for (int it = 0; it < 32; it++) {
            const int row  = wid * 16 + (it >> 1);
            const int hidx = it & 1;
            const int ghead = byn * 2 + hidx;          // 0..47
            const int t = bxm * 128 + row;

            float4 v = *reinterpret_cast<const float4*>(
                &Cs[(size_t)row * CS_STRIDE + hidx * 128 + lane * 4]);
            float xv[4] = {v.x, v.y, v.z, v.w};

            float ss = xv[0]*xv[0] + xv[1]*xv[1] + xv[2]*xv[2] + xv[3]*xv[3];
#pragma unroll
            for (int o = 16; o > 0; o >>= 1) ss += __shfl_xor_sync(0xffffffffu, ss, o);
            const float inv = rsqrtf(ss * (1.0f / 128.0f) + 1e-6f);

            int type, head;
            if (ghead < NHQ)            { type = 0; head = ghead; }
            else if (ghead < NHQ + NKV) { type = 1; head = ghead - NHQ; }
            else                        { type = 2; head = ghead - NHQ - NKV; }

            if (type == 0) {
#pragma unroll
                for (int m = 0; m < 4; m++) xv[m] *= inv * (1.0f + q_scale[lane * 4 + m]);
            } else if (type == 1) {
#pragma unroll
                for (int m = 0; m < 4; m++) xv[m] *= inv * (1.0f + k_scale[lane * 4 + m]);
            } else {
#pragma unroll
                for (int m = 0; m < 4; m++) xv[m] *= inv;
            }

            if (type < 2) {
                const float pos = (float)segment_pos[t];
                float yv[4];
#pragma unroll
                for (int m = 0; m < 4; m++) yv[m] = __shfl_xor_sync(0xffffffffu, xv[m], 16);
                const int  jb    = (lane & 15) * 4;
                const bool first = (lane < 16);
#pragma unroll
                for (int m = 0; m < 4; m++) {
                    float jf = (float)(jb + m);
                    float ts = powf(10000.0f, jf * (1.0f / 64.0f));
                    float ang = pos / ts;
                    float sn, cs;
                    sincosf(ang, &sn, &cs);
                    xv[m] = first ? (xv[m] * cs - yv[m] * sn)
                                  : (xv[m] * cs + yv[m] * sn);
                }
            }

            uint32_t hA, lA, hB, lB;
            pack_split(xv[0], xv[1], hA, lA);
            pack_split(xv[2], xv[3], hB, lB);
            const int chunk = lane >> 3, c8 = lane & 7;
            const size_t pb = ((size_t)((head * 16 + bxm) * 4 + chunk)) * PANEL_B
                            + (size_t)row * 80 + c8 * 8;
            char *dh, *dl;
            if (type == 0)      { dh = (char*)pk_qhi; dl = (char*)pk_qlo; }
            else if (type == 1) { dh = (char*)pk_khi; dl = (char*)pk_klo; }
            else                { dh = (char*)pk_vhi; dl = (char*)pk_vlo; }
            *reinterpret_cast<uint2*>(dh + pb) = make_uint2(hA, hB);
            *reinterpret_cast<uint2*>(dl + pb) = make_uint2(lA, lB);
        }
    }
}

// ---------------------------------------------------------------------------
// Kernel E: causal flash attention, split-bf16 HMMA (pass-major S-loop).
// ---------------------------------------------------------------------------
static constexpr int AT_ARR_B   = 4 * 5120;
static constexpr int AT_STAGE_B = 4 * AT_ARR_B;      // 81920
static constexpr int AT_SMEM    = 2 * AT_STAGE_B;    // 163840

__global__ __launch_bounds__(256) void attn_mma_kernel()
{
    extern __shared__ char smraw[];
    const uint32_t sb = smem_u32(smraw);
    const int tid = threadIdx.x, w = tid >> 5, lane = tid & 31;
    const int n   = blockIdx.x;
    const int qb  = 15 - (int)blockIdx.y;
    const int kvh = n >> 2;
    const int g = lane >> 2, tg = lane & 3;

    {
        const char* qh_src = (const char*)pk_qhi + ((size_t)(n * 16 + qb) * 4) * PANEL_B;
        const char* ql_src = (const char*)pk_qlo + ((size_t)(n * 16 + qb) * 4) * PANEL_B;
#pragma unroll
        for (int i = 0; i < 20; i++) {
            const int j = tid + i * 256;
            const char* src = (j < 2560) ? (qh_src + (size_t)j * 16)
                                         : (ql_src + (size_t)(j - 2560) * 16);
            cp16(sb + j * 16, src);
        }
        cp_commit();
        cp_wait<0>();
        __syncthreads();
    }

    uint32_t qh[8][4], ql[8][4];
#pragma unroll
    for (int ch = 0; ch < 4; ch++)
#pragma unroll
        for (int ks = 0; ks < 2; ks++) {
            const uint32_t a = sb + ch * PANEL_B
                             + (w * 16 + (lane & 15)) * 80 + (lane >> 4) * 16 + ks * 32;
            LDM4(qh[ch * 2 + ks], a);
            LDM4(ql[ch * 2 + ks], a + 40960);
        }
    __syncthreads();

    const int nt = 2 * qb + 2;
    auto issue = [&](int kt) {
        const uint32_t dst = sb + (kt & 1) * AT_STAGE_B;
        const size_t pb = ((size_t)(kvh * 16 + (kt >> 1)) * 4) * PANEL_B;
        const size_t ho = (size_t)(kt & 1) * 5120;
#pragma unroll
        for (int i = 0; i < 20; i++) {
            const int j = tid + i * 256;
            const int a = j / 1280;
            const int rr = j - a * 1280;
            const int c = rr / 320, wq = rr - c * 320;
            const char* base = (a == 0) ? (const char*)pk_khi
                             : (a == 1) ? (const char*)pk_klo
                             : (a == 2) ? (const char*)pk_vhi
                                        : (const char*)pk_vlo;
            cp16(dst + j * 16, base + pb + (size_t)c * PANEL_B + ho + (size_t)wq * 16);
        }
    };

    issue(0); cp_commit();
    issue(1); cp_commit();

    float m0 = -CUDART_INF_F, m1 = -CUDART_INF_F, l0 = 0.0f, l1 = 0.0f;
    float o[16][4] = {};

#pragma unroll 1
    for (int kt = 0; kt < nt; kt++) {
        cp_wait<1>();
        __syncthreads();
        const uint32_t st = sb + (kt & 1) * AT_STAGE_B;

        float s[8][4] = {};
#pragma unroll
        for (int ch = 0; ch < 4; ch++) {
            const uint32_t khc = st + ch * 5120;
            const uint32_t klc = khc + AT_ARR_B;
#pragma unroll
            for (int ks = 0; ks < 2; ks++) {
                uint32_t kh[4][4], kl[4][4];
                const uint32_t ro = ((lane & 7) + ((lane >> 4) & 1) * 8) * 80
                                  + ks * 32 + ((lane >> 3) & 1) * 16;
#pragma unroll
                for (int ng = 0; ng < 4; ng++) {
                    LDM4(kh[ng], khc + ng * 16 * 80 + ro);
                    LDM4(kl[ng], klc + ng * 16 * 80 + ro);
                }
                const int f = ch * 2 + ks;
                // pass-major: 8 independent accumulators between same-d MMAs
#pragma unroll
                for (int nf = 0; nf < 8; nf++) {
                    const uint32_t* bh = &kh[nf >> 1][(nf & 1) * 2];
                    MMA(s[nf], qh[f], bh[0], bh[1]);
                }
#pragma unroll
                for (int nf = 0; nf < 8; nf++) {
                    const uint32_t* bl = &kl[nf >> 1][(nf & 1) * 2];
                    MMA(s[nf], qh[f], bl[0], bl[1]);
                }
#pragma unroll
                for (int nf = 0; nf < 8; nf++) {
                    const uint32_t* bh = &kh[nf >> 1][(nf & 1) * 2];
                    MMA(s[nf], ql[f], bh[0], bh[1]);
                }
            }
        }

        if (kt >= 2 * qb) {
            const int row0 = qb * 128 + w * 16 + g;
            const int key0 = kt * 64 + tg * 2;
#pragma unroll
            for (int nf = 0; nf < 8; nf++) {
                const int k0 = key0 + nf * 8;
                if (k0     > row0)     s[nf][0] = -1e30f;
                if (k0 + 1 > row0)     s[nf][1] = -1e30f;
                if (k0     > row0 + 8) s[nf][2] = -1e30f;
                if (k0 + 1 > row0 + 8) s[nf][3] = -1e30f;
            }
        }

        float mx0 = -CUDART_INF_F, mx1 = -CUDART_INF_F;
#pragma unroll
        for (int nf = 0; nf < 8; nf++) {
            mx0 = fmaxf(mx0, fmaxf(s[nf][0], s[nf][1]));
            mx1 = fmaxf(mx1, fmaxf(s[nf][2], s[nf][3]));
        }
        mx0 = fmaxf(mx0, __shfl_xor_sync(0xffffffffu, mx0, 1));
        mx0 = fmaxf(mx0, __shfl_xor_sync(0xffffffffu, mx0, 2));
        mx1 = fmaxf(mx1, __shfl_xor_sync(0xffffffffu, mx1, 1));
        mx1 = fmaxf(mx1, __shfl_xor_sync(0xffffffffu, mx1, 2));
        const float mn0 = fmaxf(m0, mx0), mn1 = fmaxf(m1, mx1);
        const float al0 = __expf(m0 - mn0), al1 = __expf(m1 - mn1);
        m0 = mn0; m1 = mn1;
        float s0 = 0.0f, s1 = 0.0f;
#pragma unroll
        for (int nf = 0; nf < 8; nf++) {
            s[nf][0] = __expf(s[nf][0] - mn0); s0 += s[nf][0];
            s[nf][1] = __expf(s[nf][1] - mn0); s0 += s[nf][1];
            s[nf][2] = __expf(s[nf][2] - mn1); s1 += s[nf][2];
            s[nf][3] = __expf(s[nf][3] - mn1); s1 += s[nf][3];
        }
        s0 += __shfl_xor_sync(0xffffffffu, s0, 1);
        s0 += __shfl_xor_sync(0xffffffffu, s0, 2);
        s1 += __shfl_xor_sync(0xffffffffu, s1, 1);
        s1 += __shfl_xor_sync(0xffffffffu, s1, 2);
        l0 = l0 * al0 + s0;
        l1 = l1 * al1 + s1;

#pragma unroll
        for (int i = 0; i < 16; i++) {
            o[i][0] *= al0; o[i][1] *= al0; o[i][2] *= al1; o[i][3] *= al1;
        }

        uint32_t ph[4][4], pl[4][4];
#pragma unroll
        for (int jp = 0; jp < 4; jp++) {
            pack_split(s[2 * jp][0],     s[2 * jp][1],     ph[jp][0], pl[jp][0]);
            pack_split(s[2 * jp][2],     s[2 * jp][3],     ph[jp][1], pl[jp][1]);
            pack_split(s[2 * jp + 1][0], s[2 * jp + 1][1], ph[jp][2], pl[jp][2]);
            pack_split(s[2 * jp + 1][2], s[2 * jp + 1][3], ph[jp][3], pl[jp][3]);
        }

        const uint32_t vro = ((lane & 7) + ((lane >> 3) & 1) * 8) * 80
                           + ((lane >> 4) & 1) * 16;
#pragma unroll
        for (int jp = 0; jp < 4; jp++) {
#pragma unroll
            for (int ch = 0; ch < 4; ch++) {
                const uint32_t vhc = st + 2 * AT_ARR_B + ch * 5120;
                const uint32_t vlc = vhc + AT_ARR_B;
#pragma unroll
                for (int hs = 0; hs < 2; hs++) {
                    uint32_t vh[4], vl[4];
                    const uint32_t va = 16 * jp * 80 + hs * 32 + vro;
                    LDM4T(vh, vhc + va);
                    LDM4T(vl, vlc + va);
                    const int od = ch * 4 + hs * 2;
                    // pass-major across the two accumulators
                    MMA(o[od],     ph[jp], vh[0], vh[1]);
                    MMA(o[od + 1], ph[jp], vh[2], vh[3]);
                    MMA(o[od],     ph[jp], vl[0], vl[1]);
                    MMA(o[od + 1], ph[jp], vl[2], vl[3]);
                    MMA(o[od],     pl[jp], vh[0], vh[1]);
                    MMA(o[od + 1], pl[jp], vh[2], vh[3]);
                }
            }
        }

        __syncthreads();
        if (kt + 2 < nt) issue(kt + 2);
        cp_commit();
    }

    const float li0 = 1.0f / l0, li1 = 1.0f / l1;
    const int r_lo = w * 16 + g;
    char* ah = (char*)pk_ahi;
    char* al = (char*)pk_alo;
#pragma unroll
    for (int i = 0; i < 16; i++) {
        const int kg = n * 128 + i * 8 + tg * 2;
        const int kp = kg >> 5, cc = kg & 31;
        uint32_t h0, lo0, h1, lo1;
        pack_split(o[i][0] * li0, o[i][1] * li0, h0, lo0);
        pack_split(o[i][2] * li1, o[i][3] * li1, h1, lo1);
        const size_t base = ((size_t)(qb * KPAN + kp)) * PANEL_B + (size_t)cc * 2;
        *reinterpret_cast<uint32_t*>(ah + base + (size_t)r_lo * 80)       = h0;
        *reinterpret_cast<uint32_t*>(al + base + (size_t)r_lo * 80)       = lo0;
        *reinterpret_cast<uint32_t*>(ah + base + (size_t)(r_lo + 8) * 80) = h1;
        *reinterpret_cast<uint32_t*>(al + base + (size_t)(r_lo + 8) * 80) = lo1;
    }
}

// ---------------------------------------------------------------------------
// Launch
// ---------------------------------------------------------------------------
extern "C" void kernel_launch(void* const* d_in, const int* in_sizes, int n_in,
                              void* d_out, int out_size)
{
    const float* x    = (const float*)d_in[0];
    const int*   seg  = (const int*)  d_in[1];
    // d_in[2] = attn_mask (exactly causal; handled analytically)
    const float* q_w  = (const float*)d_in[3];
    const float* kv_w = (const float*)d_in[4];
    const float* o_w  = (const float*)d_in[5];
    const float* q_s  = (const float*)d_in[6];
    const float* k_s  = (const float*)d_in[7];
    float* out = (float*)d_out;

    cudaFuncSetAttribute((const void*)gemm_mma_kernel<0>,
                         cudaFuncAttributeMaxDynamicSharedMemorySize, GEMM_SMEM);
    cudaFuncSetAttribute((const void*)gemm_mma_kernel<1>,
                         cudaFuncAttributeMaxDynamicSharedMemorySize, GEMM_SMEM);
    cudaFuncSetAttribute((const void*)attn_mma_kernel,
                         cudaFuncAttributeMaxDynamicSharedMemorySize, AT_SMEM);

    void *p_xh, *p_xl, *p_ah, *p_al, *p_wqh, *p_wql, *p_woh, *p_wol;
    cudaGetSymbolAddress(&p_xh, pk_xhi);
    cudaGetSymbolAddress(&p_xl, pk_xlo);
    cudaGetSymbolAddress(&p_ah, pk_ahi);
    cudaGetSymbolAddress(&p_al, pk_alo);
    cudaGetSymbolAddress(&p_wqh, pk_wqh);
    cudaGetSymbolAddress(&p_wql, pk_wql);
    cudaGetSymbolAddress(&p_woh, pk_woh);
    cudaGetSymbolAddress(&p_wol, pk_wol);

    // 1) packing
    pack_x_kernel<<<(T_SEQ * 512) / 256, 256>>>(x);
    pack_wq_kernel<<<dim3(128, 4, 32), dim3(32, 8)>>>(q_w, 0);
    pack_wq_kernel<<<dim3(128, 4, 8),  dim3(32, 8)>>>(kv_w, KCOL0);
    pack_wq_kernel<<<dim3(128, 4, 8),  dim3(32, 8)>>>(
        kv_w + (size_t)NKV * D_MODEL * HD, VCOL0);
    pack_wo_kernel<<<dim3(128, 128), dim3(32, 8)>>>(o_w);

    // 2) QKV projection with FUSED norm+rope+split epilogue -> Q/K/V panels
    gemm_mma_kernel<1><<<dim3(T_SEQ / 128, NQKV / 256), 256, GEMM_SMEM>>>(
        (const char*)p_xh, (const char*)p_xl,
        (const char*)p_wqh, (const char*)p_wql,
        nullptr, 0, seg, q_s, k_s);

    // 3) flash attention (HMMA split-bf16) -> pk_ahi/alo
    attn_mma_kernel<<<dim3(NHQ, T_SEQ / 128), 256, AT_SMEM>>>();

    // 4) O projection (plain epilogue) -> d_out
    gemm_mma_kernel<0><<<dim3(T_SEQ / 128, D_MODEL / 256), 256, GEMM_SMEM>>>(
        (const char*)p_ah, (const char*)p_al,
        (const char*)p_woh, (const char*)p_wol,
        out, D_MODEL, nullptr, nullptr, nullptr);
}

// round 17
// speedup vs baseline: 1.1194x; 1.1194x over previous
#include <cuda_runtime.h>
#include <cuda_bf16.h>
#include <cuda_fp16.h>
#include <math.h>
#include <math_constants.h>
#include <stdint.h>

// ---------------------------------------------------------------------------
// Problem constants
// ---------------------------------------------------------------------------
static constexpr int T_SEQ   = 2048;
static constexpr int D_MODEL = 4096;
static constexpr int NHQ     = 32;
static constexpr int NKV     = 8;
static constexpr int HD      = 128;
static constexpr int NQKV    = NHQ * HD + 2 * NKV * HD;   // 6144
static constexpr int KCOL0   = NHQ * HD;                  // 4096
static constexpr int VCOL0   = KCOL0 + NKV * HD;          // 5120

// Packed-panel geometry: panel = [128 rows x 32 k] 16-bit, rows padded to 80B.
static constexpr int PANEL_B   = 10240;
static constexpr int PANEL_U4  = 640;
static constexpr int KPAN      = 128;      // 4096/32 k-panels per GEMM matrix

static constexpr float WO_SCALE   = 256.0f;       // o_w pre-scale (pow2, exact)
static constexpr float WO_ISCALE  = 1.0f / 256.0f;

// ---------------------------------------------------------------------------
// Scratch (device globals -- sanctioned scratch mechanism)
// ---------------------------------------------------------------------------
__device__ float g_qkv[(size_t)T_SEQ * NQKV];            // fp32 qkv (pre-norm)

__device__ uint4 pk_xhi[(size_t)16 * KPAN * PANEL_U4];   // x packed (bf16)
__device__ uint4 pk_xlo[(size_t)16 * KPAN * PANEL_U4];
__device__ uint4 pk_ahi[(size_t)16 * KPAN * PANEL_U4];   // attention out (fp16, hi only)
__device__ uint4 pk_wqh[(size_t)48 * KPAN * PANEL_U4];   // qkv weights (bf16)
__device__ uint4 pk_wql[(size_t)48 * KPAN * PANEL_U4];
__device__ uint4 pk_woh[(size_t)32 * KPAN * PANEL_U4];   // o_w (fp16, x256)
__device__ uint4 pk_wol[(size_t)32 * KPAN * PANEL_U4];

// attention operand panels (bf16, written by norm_rope):
__device__ uint4 pk_qhi[(size_t)32 * 16 * 4 * PANEL_U4];
__device__ uint4 pk_qlo[(size_t)32 * 16 * 4 * PANEL_U4];
__device__ uint4 pk_khi[(size_t)8 * 16 * 4 * PANEL_U4];
__device__ uint4 pk_klo[(size_t)8 * 16 * 4 * PANEL_U4];
__device__ uint4 pk_vhi[(size_t)8 * 16 * 4 * PANEL_U4];
__device__ uint4 pk_vlo[(size_t)8 * 16 * 4 * PANEL_U4];

// ---------------------------------------------------------------------------
// PTX helpers (sm_80-era features only; valid at compute_103 base target)
// ---------------------------------------------------------------------------
__device__ __forceinline__ uint32_t smem_u32(const void* p) {
    uint32_t a;
    asm("{ .reg .u64 t; cvta.to.shared.u64 t, %1; cvt.u32.u64 %0, t; }" : "=r"(a) : "l"(p));
    return a;
}

#define LDM4(r, a)                                                            \
    asm volatile("ldmatrix.sync.aligned.m8n8.x4.shared.b16 {%0,%1,%2,%3}, [%4];" \
        : "=r"((r)[0]), "=r"((r)[1]), "=r"((r)[2]), "=r"((r)[3]) : "r"(a))

#define LDM4T(r, a)                                                           \
    asm volatile("ldmatrix.sync.aligned.m8n8.x4.trans.shared.b16 {%0,%1,%2,%3}, [%4];" \
        : "=r"((r)[0]), "=r"((r)[1]), "=r"((r)[2]), "=r"((r)[3]) : "r"(a))

#define MMA(d, a, b0, b1)                                                     \
    asm volatile("mma.sync.aligned.m16n8k16.row.col.f32.bf16.bf16.f32 "       \
        "{%0,%1,%2,%3},{%4,%5,%6,%7},{%8,%9},{%0,%1,%2,%3};"                  \
        : "+f"((d)[0]), "+f"((d)[1]), "+f"((d)[2]), "+f"((d)[3])              \
        : "r"((a)[0]), "r"((a)[1]), "r"((a)[2]), "r"((a)[3]), "r"(b0), "r"(b1))

#define MMAH(d, a, b0, b1)                                                    \
    asm volatile("mma.sync.aligned.m16n8k16.row.col.f32.f16.f16.f32 "         \
        "{%0,%1,%2,%3},{%4,%5,%6,%7},{%8,%9},{%0,%1,%2,%3};"                  \
        : "+f"((d)[0]), "+f"((d)[1]), "+f"((d)[2]), "+f"((d)[3])              \
        : "r"((a)[0]), "r"((a)[1]), "r"((a)[2]), "r"((a)[3]), "r"(b0), "r"(b1))

__device__ __forceinline__ void cp16(uint32_t dst, const void* src) {
    asm volatile("cp.async.cg.shared.global [%0], [%1], 16;" :: "r"(dst), "l"(src));
}
__device__ __forceinline__ void cp_commit() { asm volatile("cp.async.commit_group;" ::: "memory"); }
template <int N> __device__ __forceinline__ void cp_wait() {
    asm volatile("cp.async.wait_group %0;" :: "n"(N) : "memory");
}

__device__ __forceinline__ void split2(float x, __nv_bfloat16& h, __nv_bfloat16& l) {
    h = __float2bfloat16_rn(x);
    l = __float2bfloat16_rn(x - __bfloat162float(h));
}
__device__ __forceinline__ void pack_split(float f0, float f1, uint32_t& h, uint32_t& l) {
    __nv_bfloat16 h0, l0, h1, l1;
    split2(f0, h0, l0);
    split2(f1, h1, l1);
    h = ((uint32_t)__bfloat16_as_ushort(h1) << 16) | __bfloat16_as_ushort(h0);
    l = ((uint32_t)__bfloat16_as_ushort(l1) << 16) | __bfloat16_as_ushort(l0);
}
// fp16 split (for O-projection operands)
__device__ __forceinline__ void split2h(float x, __half& h, __half& l) {
    h = __float2half_rn(x);
    l = __float2half_rn(x - __half2float(h));
}
__device__ __forceinline__ uint32_t pack_h2(float f0, float f1) {
    return ((uint32_t)__half_as_ushort(__float2half_rn(f1)) << 16)
         | __half_as_ushort(__float2half_rn(f0));
}

__device__ __forceinline__ size_t pk_idx(int row, int kchunk16) {
    const int rb = row >> 7, r = row & 127;
    const int kc = kchunk16 >> 2, c = kchunk16 & 3;
    return ((size_t)(rb * KPAN + kc)) * PANEL_U4 + r * 5 + c;
}

// ---------------------------------------------------------------------------
// Kernel A: pack x -> bf16 hi/lo panels
// ---------------------------------------------------------------------------
__global__ __launch_bounds__(256) void pack_x_kernel(const float* __restrict__ x)
{
    const int gid = blockIdx.x * 256 + threadIdx.x;
    const int row = gid >> 9, kch = gid & 511;
    const float* s = x + (size_t)row * D_MODEL + kch * 8;
    float4 a = *reinterpret_cast<const float4*>(s);
    float4 b = *reinterpret_cast<const float4*>(s + 4);
    float v[8] = {a.x, a.y, a.z, a.w, b.x, b.y, b.z, b.w};
    __nv_bfloat16 h8[8], l8[8];
#pragma unroll
    for (int i = 0; i < 8; i++) split2(v[i], h8[i], l8[i]);
    const size_t idx = pk_idx(row, kch);
    pk_xhi[idx] = *reinterpret_cast<uint4*>(h8);
    pk_xlo[idx] = *reinterpret_cast<uint4*>(l8);
}

// ---------------------------------------------------------------------------
// Kernel B1: pack qkv weights -- MERGED: grid.z = 48 covers Q(0..31),
// K(32..39), V(40..47). kv_w is [2][8][4096][128] so (z-32) indexes the
// K then V slabs contiguously. Panel row = z*128 + h.
// ---------------------------------------------------------------------------
__global__ __launch_bounds__(256) void pack_wq_kernel(
    const float* __restrict__ q_w, const float* __restrict__ kv_w)
{
    __shared__ float t[32][33];
    const int tx = threadIdx.x, ty = threadIdx.y;
    const int d0 = blockIdx.x * 32, h0 = blockIdx.y * 32, z = blockIdx.z;
    const float* s = (z < 32) ? q_w + (size_t)z * D_MODEL * HD
                              : kv_w + (size_t)(z - 32) * D_MODEL * HD;
#pragma unroll
    for (int j = 0; j < 4; j++)
        t[ty + 8 * j][tx] = s[(size_t)(d0 + ty + 8 * j) * HD + h0 + tx];
    __syncthreads();
    const int tid = ty * 32 + tx;
    if (tid < 128) {
        const int h_in = tid >> 2, cj = tid & 3;
        const int row = z * HD + h0 + h_in;
        __nv_bfloat16 h8[8], l8[8];
#pragma unroll
        for (int i = 0; i < 8; i++) split2(t[cj * 8 + i][h_in], h8[i], l8[i]);
        const size_t idx = pk_idx(row, (d0 >> 3) + cj);
        pk_wqh[idx] = *reinterpret_cast<uint4*>(h8);
        pk_wql[idx] = *reinterpret_cast<uint4*>(l8);
    }
}

// ---------------------------------------------------------------------------
// Kernel B2: pack o_w -> fp16 hi/lo, pre-scaled by 256 (pow2, exact;
// keeps the lo limb out of fp16 subnormal range). rows=d, k=nh.
// ---------------------------------------------------------------------------
__global__ __launch_bounds__(256) void pack_wo_kernel(const float* __restrict__ src)
{
    __shared__ float t[32][33];
    const int tx = threadIdx.x, ty = threadIdx.y;
    const int nh0 = blockIdx.x * 32, d0 = blockIdx.y * 32;
#pragma unroll
    for (int j = 0; j < 4; j++)
        t[ty + 8 * j][tx] = src[(size_t)(nh0 + ty + 8 * j) * D_MODEL + d0 + tx];
    __syncthreads();
    const int tid = ty * 32 + tx;
    if (tid < 128) {
        const int d_in = tid >> 2, cj = tid & 3;
        const int row = d0 + d_in;
        __half h8[8], l8[8];
#pragma unroll
        for (int i = 0; i < 8; i++) split2h(t[cj * 8 + i][d_in] * WO_SCALE, h8[i], l8[i]);
        const size_t idx = pk_idx(row, (nh0 >> 3) + cj);
        pk_woh[idx] = *reinterpret_cast<uint4*>(h8);
        pk_wol[idx] = *reinterpret_cast<uint4*>(l8);
    }
}

// ---------------------------------------------------------------------------
// Kernel C: split-bf16 HMMA GEMM (QKV), 128x256 CTA tile -- EXACT R11-best
// structure: 2-stage ring, dual barrier, interleaved 3-pass MMA order.
// ---------------------------------------------------------------------------
static constexpr int G_STAGE_B  = 6 * PANEL_B;             // 61440
static constexpr int GEMM_SMEM  = 2 * G_STAGE_B;           // 122880

__global__ __launch_bounds__(256, 1) void gemm_mma_kernel(
    const char* __restrict__ Ah, const char* __restrict__ Al,
    const char* __restrict__ Bh, const char* __restrict__ Bl,
    float* __restrict__ C, int ldc)
{
    extern __shared__ char smraw[];
    const uint32_t sb = smem_u32(smraw);
    const int tid = threadIdx.x, wid = tid >> 5, lane = tid & 31;
    const int bxm = blockIdx.x, byn = blockIdx.y;

    const char* pAh = Ah + (size_t)bxm * KPAN * PANEL_B;
    const char* pAl = Al + (size_t)bxm * KPAN * PANEL_B;
    const char* pBh0 = Bh + (size_t)(2 * byn) * KPAN * PANEL_B;
    const char* pBh1 = Bh + (size_t)(2 * byn + 1) * KPAN * PANEL_B;
    const char* pBl0 = Bl + (size_t)(2 * byn) * KPAN * PANEL_B;
    const char* pBl1 = Bl + (size_t)(2 * byn + 1) * KPAN * PANEL_B;

    auto load_stage = [&](int c) {
        const uint32_t dst = sb + (c & 1) * G_STAGE_B;
        const size_t coff = (size_t)c * PANEL_B;
#pragma unroll
        for (int i = 0; i < 15; i++) {
            const int j = tid + i * 256;
            const int r = j / PANEL_U4;
            const int w = j - r * PANEL_U4;
            const char* s =
                (r == 0) ? pAh : (r == 1) ? pAl :
                (r == 2) ? pBh0 : (r == 3) ? pBh1 :
                (r == 4) ? pBl0 : pBl1;
            cp16(dst + j * 16, s + coff + (size_t)w * 16);
        }
    };

    load_stage(0); cp_commit();
    load_stage(1); cp_commit();

    float acc[4][8][4] = {};
    const int wm = wid >> 2, wn = wid & 3;
    const uint32_t aoff = (uint32_t)((wm * 64 + (lane & 15)) * 80 + (lane >> 4) * 16);
    const uint32_t boff = (uint32_t)((wn * 64 + ((lane >> 4) << 3) + (lane & 7)) * 80
                                     + ((lane >> 3) & 1) * 16);

#pragma unroll 1
    for (int c = 0; c < KPAN; c++) {
        cp_wait<1>();
        __syncthreads();

        const uint32_t base = sb + (c & 1) * G_STAGE_B;
        const uint32_t Abh = base + aoff;
        const uint32_t Abl = Abh + PANEL_B;
        const uint32_t Bbh = base + 2 * PANEL_B + boff;
        const uint32_t Bbl = Bbh + 2 * PANEL_B;

#pragma unroll
        for (int ks = 0; ks < 2; ks++) {
            uint32_t ah[4][4], al[4][4];
#pragma unroll
            for (int mf = 0; mf < 4; mf++) {
                LDM4(ah[mf], Abh + ks * 32 + mf * 1280);
                LDM4(al[mf], Abl + ks * 32 + mf * 1280);
            }
#pragma unroll
            for (int ng = 0; ng < 4; ng++) {
                uint32_t bh[4], bl[4];
                LDM4(bh, Bbh + ks * 32 + ng * 1280);
                LDM4(bl, Bbl + ks * 32 + ng * 1280);
#pragma unroll
                for (int mf = 0; mf < 4; mf++) {
#pragma unroll
                    for (int hf = 0; hf < 2; hf++) {
                        float* d = acc[mf][ng * 2 + hf];
                        MMA(d, ah[mf], bh[hf * 2], bh[hf * 2 + 1]);
                        MMA(d, ah[mf], bl[hf * 2], bl[hf * 2 + 1]);
                        MMA(d, al[mf], bh[hf * 2], bh[hf * 2 + 1]);
                    }
                }
            }
        }
        __syncthreads();
        if (c + 2 < KPAN) load_stage(c + 2);
        cp_commit();
    }

    const int g = lane >> 2, tg = lane & 3;
#pragma unroll
    for (int mf = 0; mf < 4; mf++)
#pragma unroll
        for (int nf = 0; nf < 8; nf++) {
            const int r0  = bxm * 128 + wm * 64 + mf * 16 + g;
            const int col = byn * 256 + wn * 64 + nf * 8 + tg * 2;
            *reinterpret_cast<float2*>(C + (size_t)r0 * ldc + col) =
                make_float2(acc[mf][nf][0], acc[mf][nf][1]);
            *reinterpret_cast<float2*>(C + (size_t)(r0 + 8) * ldc + col) =
                make_float2(acc[mf][nf][2], acc[mf][nf][3]);
        }
}

// ---------------------------------------------------------------------------
// Kernel C2: O-projection GEMM, fp16 2-pass.  A = fp16 attention-out (hi
// only), W = fp16 hi+lo (x256).  out = (A*Wh + A*Wl)/256.  Stage = 5 panels.
// ---------------------------------------------------------------------------
static constexpr int O_STAGE_B = 5 * PANEL_B;              // 51200
static constexpr int O_SMEM    = 2 * O_STAGE_B;            // 102400

__global__ __launch_bounds__(256, 1) void gemm_o_kernel(
    const char* __restrict__ Ah,
    const char* __restrict__ Wh, const char* __restrict__ Wl,
    float* __restrict__ C, int ldc)
{
    extern __shared__ char smraw[];
    const uint32_t sb = smem_u32(smraw);
    const int tid = threadIdx.x, wid = tid >> 5, lane = tid & 31;
    const int bxm = blockIdx.x, byn = blockIdx.y;

    const char* pAh = Ah + (size_t)bxm * KPAN * PANEL_B;
    const char* pWh0 = Wh + (size_t)(2 * byn) * KPAN * PANEL_B;
    const char* pWh1 = Wh + (size_t)(2 * byn + 1) * KPAN * PANEL_B;
    const char* pWl0 = Wl + (size_t)(2 * byn) * KPAN * PANEL_B;
    const char* pWl1 = Wl + (size_t)(2 * byn + 1) * KPAN * PANEL_B;

    // stage layout (bytes): Ah @0, Wh @10240 (2 panels), Wl @30720 (2 panels)
    auto load_stage = [&](int c) {
        const uint32_t dst = sb + (c & 1) * O_STAGE_B;
        const size_t coff = (size_t)c * PANEL_B;
#pragma unroll
        for (int i = 0; i < 13; i++) {
            const int j = tid + i * 256;
            if (j < 3200) {
                const int r = j / PANEL_U4;
                const int w = j - r * PANEL_U4;
                const char* s =
                    (r == 0) ? pAh : (r == 1) ? pWh0 :
                    (r == 2) ? pWh1 : (r == 3) ? pWl0 : pWl1;
                cp16(dst + j * 16, s + coff + (size_t)w * 16);
            }
        }
    };

    load_stage(0); cp_commit();
    load_stage(1); cp_commit();

    float acc[4][8][4] = {};
    const int wm = wid >> 2, wn = wid & 3;
    const uint32_t aoff = (uint32_t)((wm * 64 + (lane & 15)) * 80 + (lane >> 4) * 16);
    const uint32_t boff = (uint32_t)((wn * 64 + ((lane >> 4) << 3) + (lane & 7)) * 80
                                     + ((lane >> 3) & 1) * 16);

#pragma unroll 1
    for (int c = 0; c < KPAN; c++) {
        cp_wait<1>();
        __syncthreads();

        const uint32_t base = sb + (c & 1) * O_STAGE_B;
        const uint32_t Ab  = base + aoff;
        const uint32_t Wbh = base + PANEL_B + boff;
        const uint32_t Wbl = Wbh + 2 * PANEL_B;

#pragma unroll
        for (int ks = 0; ks < 2; ks++) {
            uint32_t af[4][4];
#pragma unroll
            for (int mf = 0; mf < 4; mf++)
                LDM4(af[mf], Ab + ks * 32 + mf * 1280);
#pragma unroll
            for (int ng = 0; ng < 4; ng++) {
                uint32_t wh[4], wl[4];
                LDM4(wh, Wbh + ks * 32 + ng * 1280);
                LDM4(wl, Wbl + ks * 32 + ng * 1280);
#pragma unroll
                for (int mf = 0; mf < 4; mf++) {
#pragma unroll
                    for (int hf = 0; hf < 2; hf++) {
                        float* d = acc[mf][ng * 2 + hf];
                        MMAH(d, af[mf], wh[hf * 2], wh[hf * 2 + 1]);
                        MMAH(d, af[mf], wl[hf * 2], wl[hf * 2 + 1]);
                    }
                }
            }
        }
        __syncthreads();
        if (c + 2 < KPAN) load_stage(c + 2);
        cp_commit();
    }

    const int g = lane >> 2, tg = lane & 3;
#pragma unroll
    for (int mf = 0; mf < 4; mf++)
#pragma unroll
        for (int nf = 0; nf < 8; nf++) {
            const int r0  = bxm * 128 + wm * 64 + mf * 16 + g;
            const int col = byn * 256 + wn * 64 + nf * 8 + tg * 2;
            *reinterpret_cast<float2*>(C + (size_t)r0 * ldc + col) =
                make_float2(acc[mf][nf][0] * WO_ISCALE, acc[mf][nf][1] * WO_ISCALE);
            *reinterpret_cast<float2*>(C + (size_t)(r0 + 8) * ldc + col) =
                make_float2(acc[mf][nf][2] * WO_ISCALE, acc[mf][nf][3] * WO_ISCALE);
        }
}

// ---------------------------------------------------------------------------
// Kernel D: RMSNorm (+scale) + RoPE; reads fp32 g_qkv, writes bf16 hi/lo
// Q/K/V panels for the HMMA attention kernel.  (R11-best version.)
// ---------------------------------------------------------------------------
__global__ __launch_bounds__(256) void norm_rope_kernel(
    const int*   __restrict__ segment_pos,
    const float* __restrict__ q_scale,
    const float* __restrict__ k_scale)
{
    const int gw   = (blockIdx.x * blockDim.x + threadIdx.x) >> 5;
    const int lane = threadIdx.x & 31;
    const int t    = gw / 48;
    if (t >= T_SEQ) return;
    const int hv   = gw - t * 48;

    int col, type, head;
    if (hv < NHQ)            { type = 0; head = hv;            col = hv * HD; }
    else if (hv < NHQ + NKV) { type = 1; head = hv - NHQ;      col = KCOL0 + head * HD; }
    else                     { type = 2; head = hv - NHQ - NKV; col = VCOL0 + head * HD; }

    const float* p = g_qkv + (size_t)t * NQKV + col + lane * 4;
    float4 v = *reinterpret_cast<const float4*>(p);

    float ss = v.x * v.x + v.y * v.y + v.z * v.z + v.w * v.w;
#pragma unroll
    for (int o = 16; o > 0; o >>= 1) ss += __shfl_xor_sync(0xffffffffu, ss, o);
    const float inv = rsqrtf(ss * (1.0f / 128.0f) + 1e-6f);

    float xv[4] = {v.x, v.y, v.z, v.w};
    if (type == 0) {
#pragma unroll
        for (int m = 0; m < 4; m++) xv[m] *= inv * (1.0f + q_scale[lane * 4 + m]);
    } else if (type == 1) {
#pragma unroll
        for (int m = 0; m < 4; m++) xv[m] *= inv * (1.0f + k_scale[lane * 4 + m]);
    } else {
#pragma unroll
        for (int m = 0; m < 4; m++) xv[m] *= inv;
    }

    if (type < 2) {
        const float pos = (float)segment_pos[t];
        float yv[4];
#pragma unroll
        for (int m = 0; m < 4; m++) yv[m] = __shfl_xor_sync(0xffffffffu, xv[m], 16);
        const int  jb    = (lane & 15) * 4;
        const bool first = (lane < 16);
#pragma unroll
        for (int m = 0; m < 4; m++) {
            float jf = (float)(jb + m);
            float ts = powf(10000.0f, jf * (1.0f / 64.0f));
            float ang = pos / ts;
            float sn, cs;
            sincosf(ang, &sn, &cs);
            xv[m] = first ? (xv[m] * cs - yv[m] * sn)
                          : (xv[m] * cs + yv[m] * sn);
        }
    }

    uint32_t hA, lA, hB, lB;
    pack_split(xv[0], xv[1], hA, lA);
    pack_split(xv[2], xv[3], hB, lB);
    const int rb = t >> 7, r = t & 127;
    const int chunk = lane >> 3, c8 = lane & 7;
    const size_t pb = ((size_t)((head * 16 + rb) * 4 + chunk)) * PANEL_B
                    + (size_t)r * 80 + c8 * 8;
    char *dh, *dl;
    if (type == 0)      { dh = (char*)pk_qhi; dl = (char*)pk_qlo; }
    else if (type == 1) { dh = (char*)pk_khi; dl = (char*)pk_klo; }
    else                { dh = (char*)pk_vhi; dl = (char*)pk_vlo; }
    *reinterpret_cast<uint2*>(dh + pb) = make_uint2(hA, hB);
    *reinterpret_cast<uint2*>(dl + pb) = make_uint2(lA, lB);
}

// ---------------------------------------------------------------------------
// Kernel E: causal flash attention, split-bf16 HMMA (R11-best structure).
// Epilogue: fp16 a-hi only (no lo limb) for the 2-pass O projection.
// ---------------------------------------------------------------------------
static constexpr int AT_ARR_B   = 4 * 5120;
static constexpr int AT_STAGE_B = 4 * AT_ARR_B;      // 81920
static constexpr int AT_SMEM    = 2 * AT_STAGE_B;    // 163840

__global__ __launch_bounds__(256) void attn_mma_kernel()
{
    extern __shared__ char smraw[];
    const uint32_t sb = smem_u32(smraw);
    const int tid = threadIdx.x, w = tid >> 5, lane = tid & 31;
    const int n   = blockIdx.x;
    const int qb  = 15 - (int)blockIdx.y;
    const int kvh = n >> 2;
    const int g = lane >> 2, tg = lane & 3;

    {
        const char* qh_src = (const char*)pk_qhi + ((size_t)(n * 16 + qb) * 4) * PANEL_B;
        const char* ql_src = (const char*)pk_qlo + ((size_t)(n * 16 + qb) * 4) * PANEL_B;
#pragma unroll
        for (int i = 0; i < 20; i++) {
            const int j = tid + i * 256;
            const char* src = (j < 2560) ? (qh_src + (size_t)j * 16)
                                         : (ql_src + (size_t)(j - 2560) * 16);
            cp16(sb + j * 16, src);
        }
        cp_commit();
        cp_wait<0>();
        __syncthreads();
    }

    uint32_t qh[8][4], ql[8][4];
#pragma unroll
    for (int ch = 0; ch < 4; ch++)
#pragma unroll
        for (int ks = 0; ks < 2; ks++) {
            const uint32_t a = sb + ch * PANEL_B
                             + (w * 16 + (lane & 15)) * 80 + (lane >> 4) * 16 + ks * 32;
            LDM4(qh[ch * 2 + ks], a);
            LDM4(ql[ch * 2 + ks], a + 40960);
        }
    __syncthreads();

    const int nt = 2 * qb + 2;
    auto issue = [&](int kt) {
        const uint32_t dst = sb + (kt & 1) * AT_STAGE_B;
        const size_t pb = ((size_t)(kvh * 16 + (kt >> 1)) * 4) * PANEL_B;
        const size_t ho = (size_t)(kt & 1) * 5120;
#pragma unroll
        for (int i = 0; i < 20; i++) {
            const int j = tid + i * 256;
            const int a = j / 1280;
            const int rr = j - a * 1280;
            const int c = rr / 320, wq = rr - c * 320;
            const char* base = (a == 0) ? (const char*)pk_khi
                             : (a == 1) ? (const char*)pk_klo
                             : (a == 2) ? (const char*)pk_vhi
                                        : (const char*)pk_vlo;
            cp16(dst + j * 16, base + pb + (size_t)c * PANEL_B + ho + (size_t)wq * 16);
        }
    };

    issue(0); cp_commit();
    issue(1); cp_commit();

    float m0 = -CUDART_INF_F, m1 = -CUDART_INF_F, l0 = 0.0f, l1 = 0.0f;
    float o[16][4] = {};

#pragma unroll 1
    for (int kt = 0; kt < nt; kt++) {
        cp_wait<1>();
        __syncthreads();
        const uint32_t st = sb + (kt & 1) * AT_STAGE_B;

        float s[8][4] = {};
#pragma unroll
        for (int ch = 0; ch < 4; ch++) {
            const uint32_t khc = st + ch * 5120;
            const uint32_t klc = khc + AT_ARR_B;
#pragma unroll
            for (int ks = 0; ks < 2; ks++) {
                uint32_t kh[4][4], kl[4][4];
                const uint32_t ro = ((lane & 7) + ((lane >> 4) & 1) * 8) * 80
                                  + ks * 32 + ((lane >> 3) & 1) * 16;
#pragma unroll
                for (int ng = 0; ng < 4; ng++) {
                    LDM4(kh[ng], khc + ng * 16 * 80 + ro);
                    LDM4(kl[ng], klc + ng * 16 * 80 + ro);
                }
                const int f = ch * 2 + ks;
#pragma unroll
                for (int nf = 0; nf < 8; nf++) {
                    const uint32_t* bh = &kh[nf >> 1][(nf & 1) * 2];
                    const uint32_t* bl = &kl[nf >> 1][(nf & 1) * 2];
                    MMA(s[nf], qh[f], bh[0], bh[1]);
                    MMA(s[nf], qh[f], bl[0], bl[1]);
                    MMA(s[nf], ql[f], bh[0], bh[1]);
                }
            }
        }

        if (kt >= 2 * qb) {
            const int row0 = qb * 128 + w * 16 + g;
            const int key0 = kt * 64 + tg * 2;
#pragma unroll
            for (int nf = 0; nf < 8; nf++) {
                const int k0 = key0 + nf * 8;
                if (k0     > row0)     s[nf][0] = -1e30f;
                if (k0 + 1 > row0)     s[nf][1] = -1e30f;
                if (k0     > row0 + 8) s[nf][2] = -1e30f;
                if (k0 + 1 > row0 + 8) s[nf][3] = -1e30f;
            }
        }

        float mx0 = -CUDART_INF_F, mx1 = -CUDART_INF_F;
#pragma unroll
        for (int nf = 0; nf < 8; nf++) {
            mx0 = fmaxf(mx0, fmaxf(s[nf][0], s[nf][1]));
            mx1 = fmaxf(mx1, fmaxf(s[nf][2], s[nf][3]));
        }
        mx0 = fmaxf(mx0, __shfl_xor_sync(0xffffffffu, mx0, 1));
        mx0 = fmaxf(mx0, __shfl_xor_sync(0xffffffffu, mx0, 2));
        mx1 = fmaxf(mx1, __shfl_xor_sync(0xffffffffu, mx1, 1));
        mx1 = fmaxf(mx1, __shfl_xor_sync(0xffffffffu, mx1, 2));
        const float mn0 = fmaxf(m0, mx0), mn1 = fmaxf(m1, mx1);
        const float al0 = __expf(m0 - mn0), al1 = __expf(m1 - mn1);
        m0 = mn0; m1 = mn1;
        float s0 = 0.0f, s1 = 0.0f;
#pragma unroll
        for (int nf = 0; nf < 8; nf++) {
            s[nf][0] = __expf(s[nf][0] - mn0); s0 += s[nf][0];
            s[nf][1] = __expf(s[nf][1] - mn0); s0 += s[nf][1];
            s[nf][2] = __expf(s[nf][2] - mn1); s1 += s[nf][2];
            s[nf][3] = __expf(s[nf][3] - mn1); s1 += s[nf][3];
        }
        s0 += __shfl_xor_sync(0xffffffffu, s0, 1);
        s0 += __shfl_xor_sync(0xffffffffu, s0, 2);
        s1 += __shfl_xor_sync(0xffffffffu, s1, 1);
        s1 += __shfl_xor_sync(0xffffffffu, s1, 2);
        l0 = l0 * al0 + s0;
        l1 = l1 * al1 + s1;

#pragma unroll
        for (int i = 0; i < 16; i++) {
            o[i][0] *= al0; o[i][1] *= al0; o[i][2] *= al1; o[i][3] *= al1;
        }

        uint32_t ph[4][4], pl[4][4];
#pragma unroll
        for (int jp = 0; jp < 4; jp++) {
            pack_split(s[2 * jp][0],     s[2 * jp][1],     ph[jp][0], pl[jp][0]);
            pack_split(s[2 * jp][2],     s[2 * jp][3],     ph[jp][1], pl[jp][1]);
            pack_split(s[2 * jp + 1][0], s[2 * jp + 1][1], ph[jp][2], pl[jp][2]);
            pack_split(s[2 * jp + 1][2], s[2 * jp + 1][3], ph[jp][3], pl[jp][3]);
        }

        const uint32_t vro = ((lane & 7) + ((lane >> 3) & 1) * 8) * 80
                           + ((lane >> 4) & 1) * 16;
#pragma unroll
        for (int jp = 0; jp < 4; jp++) {
#pragma unroll
            for (int ch = 0; ch < 4; ch++) {
                const uint32_t vhc = st + 2 * AT_ARR_B + ch * 5120;
                const uint32_t vlc = vhc + AT_ARR_B;
#pragma unroll
                for (int hs = 0; hs < 2; hs++) {
                    uint32_t vh[4], vl[4];
                    const uint32_t va = 16 * jp * 80 + hs * 32 + vro;
                    LDM4T(vh, vhc + va);
                    LDM4T(vl, vlc + va);
                    const int od = ch * 4 + hs * 2;
                    MMA(o[od],     ph[jp], vh[0], vh[1]);
                    MMA(o[od],     ph[jp], vl[0], vl[1]);
                    MMA(o[od],     pl[jp], vh[0], vh[1]);
                    MMA(o[od + 1], ph[jp], vh[2], vh[3]);
                    MMA(o[od + 1], ph[jp], vl[2], vl[3]);
                    MMA(o[od + 1], pl[jp], vh[2], vh[3]);
                }
            }
        }

        __syncthreads();
        if (kt + 2 < nt) issue(kt + 2);
        cp_commit();
    }

    // ---- epilogue: O/l -> fp16 hi-only panels for the 2-pass O-projection ----
    const float li0 = 1.0f / l0, li1 = 1.0f / l1;
    const int r_lo = w * 16 + g;
    char* ah = (char*)pk_ahi;
#pragma unroll
    for (int i = 0; i < 16; i++) {
        const int kg = n * 128 + i * 8 + tg * 2;
        const int kp = kg >> 5, cc = kg & 31;
        const uint32_t h0 = pack_h2(o[i][0] * li0, o[i][1] * li0);
        const uint32_t h1 = pack_h2(o[i][2] * li1, o[i][3] * li1);
        const size_t base = ((size_t)(qb * KPAN + kp)) * PANEL_B + (size_t)cc * 2;
        *reinterpret_cast<uint32_t*>(ah + base + (size_t)r_lo * 80)       = h0;
        *reinterpret_cast<uint32_t*>(ah + base + (size_t)(r_lo + 8) * 80) = h1;
    }
}

// ---------------------------------------------------------------------------
// Launch
// ---------------------------------------------------------------------------
extern "C" void kernel_launch(void* const* d_in, const int* in_sizes, int n_in,
                              void* d_out, int out_size)
{
    const float* x    = (const float*)d_in[0];
    const int*   seg  = (const int*)  d_in[1];
    // d_in[2] = attn_mask (exactly causal; handled analytically)
    const float* q_w  = (const float*)d_in[3];
    const float* kv_w = (const float*)d_in[4];
    const float* o_w  = (const float*)d_in[5];
    const float* q_s  = (const float*)d_in[6];
    const float* k_s  = (const float*)d_in[7];
    float* out = (float*)d_out;

    cudaFuncSetAttribute((const void*)gemm_mma_kernel,
                         cudaFuncAttributeMaxDynamicSharedMemorySize, GEMM_SMEM);
    cudaFuncSetAttribute((const void*)gemm_o_kernel,
                         cudaFuncAttributeMaxDynamicSharedMemorySize, O_SMEM);
    cudaFuncSetAttribute((const void*)attn_mma_kernel,
                         cudaFuncAttributeMaxDynamicSharedMemorySize, AT_SMEM);

    void *p_xh, *p_xl, *p_ah, *p_wqh, *p_wql, *p_woh, *p_wol, *p_qkv;
    cudaGetSymbolAddress(&p_xh, pk_xhi);
    cudaGetSymbolAddress(&p_xl, pk_xlo);
    cudaGetSymbolAddress(&p_ah, pk_ahi);
    cudaGetSymbolAddress(&p_wqh, pk_wqh);
    cudaGetSymbolAddress(&p_wql, pk_wql);
    cudaGetSymbolAddress(&p_woh, pk_woh);
    cudaGetSymbolAddress(&p_wol, pk_wol);
    cudaGetSymbolAddress(&p_qkv, g_qkv);

    // 1) packing
    pack_x_kernel<<<(T_SEQ * 512) / 256, 256>>>(x);
    pack_wq_kernel<<<dim3(128, 4, 48), dim3(32, 8)>>>(q_w, kv_w);
    pack_wo_kernel<<<dim3(128, 128), dim3(32, 8)>>>(o_w);

    // 2) QKV projection (bf16 3-pass, 128x256, 2-stage) -> g_qkv fp32
    gemm_mma_kernel<<<dim3(T_SEQ / 128, NQKV / 256), 256, GEMM_SMEM>>>(
        (const char*)p_xh, (const char*)p_xl,
        (const char*)p_wqh, (const char*)p_wql,
        (float*)p_qkv, NQKV);

    // 3) norm + rope -> bf16 hi/lo Q/K/V panels
    norm_rope_kernel<<<(T_SEQ * 48) / 8, 256>>>(seg, q_s, k_s);

    // 4) flash attention (bf16 3-pass) -> fp16 a-hi panels
    attn_mma_kernel<<<dim3(NHQ, T_SEQ / 128), 256, AT_SMEM>>>();

    // 5) O projection (fp16 2-pass) -> d_out
    gemm_o_kernel<<<dim3(T_SEQ / 128, D_MODEL / 256), 256, O_SMEM>>>(
        (const char*)p_ah, (const char*)p_woh, (const char*)p_wol,
        out, D_MODEL);
}